// round 1
// baseline (speedup 1.0000x reference)
#include <cuda_runtime.h>
#include <math.h>

// ---------------- problem constants ----------------
#define TOK   50176          // 64 * 784  (= 1024 windows * 49)
#define CH    512
#define C3    1536
#define FF    2048
#define NHD   16
#define HD    32
#define NWIN  1024           // 64 * 16
#define NTOKW 49

// ---------------- device scratch ----------------
__device__ float g_wqkv[CH * C3];     // K-major effective qkv weight  [K][N]
__device__ float g_wproj[CH * CH];
__device__ float g_wfc1[CH * FF];
__device__ float g_wfc2[FF * CH];
__device__ float g_xw  [(size_t)TOK * CH];   // LN1 + shift + window-partitioned
__device__ float g_qkv [(size_t)TOK * C3];
__device__ float g_attn[(size_t)TOK * CH];   // attention output (windowed order)
__device__ float g_x2  [(size_t)TOK * CH];   // residual 1 (natural order)
__device__ float g_xn2 [(size_t)TOK * CH];
__device__ float g_hbuf[(size_t)TOK * FF];   // fc1+gelu output

// ---------------- weight fusion: Wt[k][n] = W[n][k] + sum_r lb[n][r]*la[r][k] ----------------
__global__ void fuse_w_kernel(const float* __restrict__ W, const float* __restrict__ la,
                              const float* __restrict__ lb, float* __restrict__ Wt,
                              int N, int K) {
    int idx = blockIdx.x * blockDim.x + threadIdx.x;   // idx = k*N + n (coalesced write)
    if (idx >= N * K) return;
    int k = idx / N, n = idx - k * N;
    float acc = W[(size_t)n * K + k];
#pragma unroll
    for (int r = 0; r < 16; r++) acc += lb[n * 16 + r] * la[r * K + k];
    Wt[idx] = acc;
}

// ---------------- layernorm (optionally with shift + window-partition gather) ----------------
template <bool GATHER>
__global__ void ln_kernel(const float* __restrict__ x, const float* __restrict__ s,
                          const float* __restrict__ b, float* __restrict__ out) {
    int t = blockIdx.x;                 // output row
    const float* row;
    if (GATHER) {
        int wnd = t / NTOKW, n = t - wnd * NTOKW;
        int bb = wnd >> 4, wl = wnd & 15;
        int wh = wl >> 2, ww = wl & 3;
        int i = n / 7, j = n - i * 7;
        int hs = wh * 7 + i, ws = ww * 7 + j;
        int h = hs + 3; if (h >= 28) h -= 28;   // roll(-3): src = (hs+3) mod 28
        int wc = ws + 3; if (wc >= 28) wc -= 28;
        row = x + ((size_t)bb * 784 + h * 28 + wc) * CH;
    } else {
        row = x + (size_t)t * CH;
    }
    int tid = threadIdx.x;              // 256 threads, 2 channels each
    float v0 = row[tid], v1 = row[tid + 256];
    float sum = v0 + v1, sq = v0 * v0 + v1 * v1;
#pragma unroll
    for (int o = 16; o > 0; o >>= 1) {
        sum += __shfl_xor_sync(0xffffffffu, sum, o);
        sq  += __shfl_xor_sync(0xffffffffu, sq, o);
    }
    __shared__ float ssum[8], ssq[8];
    if ((tid & 31) == 0) { ssum[tid >> 5] = sum; ssq[tid >> 5] = sq; }
    __syncthreads();
    float tsum = 0.f, tsq = 0.f;
#pragma unroll
    for (int i = 0; i < 8; i++) { tsum += ssum[i]; tsq += ssq[i]; }
    float mean = tsum * (1.f / CH);
    float var  = tsq * (1.f / CH) - mean * mean;
    float rstd = rsqrtf(var + 1e-5f);
    float* orow = out + (size_t)t * CH;
    orow[tid]       = (v0 - mean) * rstd * s[tid]       + b[tid];
    orow[tid + 256] = (v1 - mean) * rstd * s[tid + 256] + b[tid + 256];
}

// ---------------- windowed attention: one block per (window, head) ----------------
__global__ void attn_kernel(const float* __restrict__ rpb) {
    int w  = blockIdx.x;
    int hh = blockIdx.y;
    __shared__ float q[NTOKW * HD], k[NTOKW * HD], v[NTOKW * HD];
    __shared__ float sc[NTOKW][NTOKW + 1];
    __shared__ int   regid[NTOKW];
    int tid = threadIdx.x;              // 256 threads
    size_t base = (size_t)w * NTOKW * C3;

    for (int idx = tid; idx < NTOKW * HD; idx += 256) {
        int n = idx >> 5, d = idx & 31;
        size_t off = base + (size_t)n * C3 + hh * HD + d;
        q[idx] = g_qkv[off];
        k[idx] = g_qkv[off + CH];
        v[idx] = g_qkv[off + 2 * CH];
    }
    if (tid < NTOKW) {
        int wl = w & 15, wh = wl >> 2, ww = wl & 3;
        int i = tid / 7, j = tid - i * 7;
        int hs = wh * 7 + i, ws = ww * 7 + j;
        int rh = hs < 21 ? 0 : (hs < 25 ? 1 : 2);
        int rw = ws < 21 ? 0 : (ws < 25 ? 1 : 2);
        regid[tid] = rh * 3 + rw;
    }
    __syncthreads();

    const float scale = 0.1767766952966369f;   // 32^-0.5
    for (int idx = tid; idx < NTOKW * NTOKW; idx += 256) {
        int n = idx / NTOKW, m = idx - n * NTOKW;
        float acc = 0.f;
#pragma unroll
        for (int d = 0; d < HD; d++) acc += q[n * HD + d] * k[m * HD + d];
        int i1 = n / 7, j1 = n - i1 * 7;
        int i2 = m / 7, j2 = m - i2 * 7;
        int ridx = (i1 - i2 + 6) * 13 + (j1 - j2 + 6);
        float bias = rpb[ridx * NHD + hh];
        float mval = (regid[n] != regid[m]) ? -100.f : 0.f;
        sc[n][m] = acc * scale + bias + mval;
    }
    __syncthreads();

    if (tid < NTOKW) {
        float mx = -1e30f;
        for (int m = 0; m < NTOKW; m++) mx = fmaxf(mx, sc[tid][m]);
        float s = 0.f;
        for (int m = 0; m < NTOKW; m++) { float e = __expf(sc[tid][m] - mx); sc[tid][m] = e; s += e; }
        float inv = 1.f / s;
        for (int m = 0; m < NTOKW; m++) sc[tid][m] *= inv;
    }
    __syncthreads();

    for (int idx = tid; idx < NTOKW * HD; idx += 256) {
        int n = idx >> 5, d = idx & 31;
        float acc = 0.f;
#pragma unroll
        for (int m = 0; m < NTOKW; m++) acc += sc[n][m] * v[m * HD + d];
        g_attn[(size_t)(w * NTOKW + n) * CH + hh * HD + d] = acc;
    }
}

// ---------------- SGEMM: C[M,N] = A[M,K] * Bt[K,N] + bias, fused epilogues ----------------
// EPI: 0 = bias only, 1 = bias + GELU(exact), 2 = proj (window-reverse scatter + residual),
//      3 = bias + residual add (same row)
#define BM 128
#define BN 128
#define BKK 8
#define TM 8
#define TN 8

__device__ __forceinline__ float gelu_exact(float x) {
    return 0.5f * x * (1.0f + erff(x * 0.70710678118654752f));
}

template <int EPI>
__global__ __launch_bounds__(256, 2)
void sgemm128(const float* __restrict__ A, const float* __restrict__ Bt,
              const float* __restrict__ bias, const float* __restrict__ res,
              float* __restrict__ C, int M, int N, int K) {
    __shared__ float As[BKK][BM];
    __shared__ float Bs[BKK][BN];
    int tid = threadIdx.x;
    int tx = tid & 15, ty = tid >> 4;
    int bm = blockIdx.y * BM, bn = blockIdx.x * BN;

    float acc[TM][TN] = {};
    int aRow = tid >> 1, aCol = (tid & 1) * 4;
    int bRow = tid >> 5, bCol = (tid & 31) * 4;
    const float* Aptr = A + (size_t)(bm + aRow) * K + aCol;
    const float* Bptr = Bt + (size_t)bRow * N + bn + bCol;

    for (int k0 = 0; k0 < K; k0 += BKK) {
        float4 a4 = *reinterpret_cast<const float4*>(Aptr);
        As[aCol + 0][aRow] = a4.x;
        As[aCol + 1][aRow] = a4.y;
        As[aCol + 2][aRow] = a4.z;
        As[aCol + 3][aRow] = a4.w;
        *reinterpret_cast<float4*>(&Bs[bRow][bCol]) =
            *reinterpret_cast<const float4*>(Bptr);
        __syncthreads();
#pragma unroll
        for (int kk = 0; kk < BKK; kk++) {
            float ra[TM], rb[TN];
            float4 t0 = *reinterpret_cast<const float4*>(&As[kk][ty * TM]);
            float4 t1 = *reinterpret_cast<const float4*>(&As[kk][ty * TM + 4]);
            ra[0] = t0.x; ra[1] = t0.y; ra[2] = t0.z; ra[3] = t0.w;
            ra[4] = t1.x; ra[5] = t1.y; ra[6] = t1.z; ra[7] = t1.w;
            float4 u0 = *reinterpret_cast<const float4*>(&Bs[kk][tx * TN]);
            float4 u1 = *reinterpret_cast<const float4*>(&Bs[kk][tx * TN + 4]);
            rb[0] = u0.x; rb[1] = u0.y; rb[2] = u0.z; rb[3] = u0.w;
            rb[4] = u1.x; rb[5] = u1.y; rb[6] = u1.z; rb[7] = u1.w;
#pragma unroll
            for (int i = 0; i < TM; i++)
#pragma unroll
                for (int j = 0; j < TN; j++)
                    acc[i][j] = fmaf(ra[i], rb[j], acc[i][j]);
        }
        __syncthreads();
        Aptr += BKK;
        Bptr += (size_t)BKK * N;
    }

    // epilogue
    int colBase = bn + tx * TN;
    float bv[TN];
#pragma unroll
    for (int j = 0; j < TN; j++) bv[j] = bias[colBase + j];

    if (EPI == 2) {
        // window-reverse + reverse-shift scatter, plus residual from res (original x)
#pragma unroll
        for (int r = 0; r < TM; r++) {
            int m = bm + ty * TM + r;
            int wnd = m / NTOKW, n = m - wnd * NTOKW;
            int bb = wnd >> 4, wl = wnd & 15;
            int wh = wl >> 2, ww = wl & 3;
            int i = n / 7, j = n - i * 7;
            int hs = wh * 7 + i, ws = ww * 7 + j;
            int h = hs + 3; if (h >= 28) h -= 28;
            int wc = ws + 3; if (wc >= 28) wc -= 28;
            size_t dest = (size_t)(bb * 784 + h * 28 + wc);
            float* crow = C + dest * N + colBase;
            const float* xrow = res + dest * N + colBase;
#pragma unroll
            for (int c = 0; c < TN; c++)
                crow[c] = xrow[c] + acc[r][c] + bv[c];
        }
    } else {
#pragma unroll
        for (int r = 0; r < TM; r++) {
            size_t off = (size_t)(bm + ty * TM + r) * N + colBase;
#pragma unroll
            for (int c = 0; c < TN; c++) {
                float val = acc[r][c] + bv[c];
                if (EPI == 1) val = gelu_exact(val);
                if (EPI == 3) val += res[off + c];
                C[off + c] = val;
            }
        }
    }
}

// ---------------- launch ----------------
extern "C" void kernel_launch(void* const* d_in, const int* in_sizes, int n_in,
                              void* d_out, int out_size) {
    const float* x      = (const float*)d_in[0];
    const float* ln1_s  = (const float*)d_in[1];
    const float* ln1_b  = (const float*)d_in[2];
    const float* qkv_w  = (const float*)d_in[3];
    const float* qkv_b  = (const float*)d_in[4];
    const float* qkv_la = (const float*)d_in[5];
    const float* qkv_lb = (const float*)d_in[6];
    const float* rpb    = (const float*)d_in[7];
    const float* proj_w = (const float*)d_in[8];
    const float* proj_b = (const float*)d_in[9];
    const float* proj_la= (const float*)d_in[10];
    const float* proj_lb= (const float*)d_in[11];
    const float* ln2_s  = (const float*)d_in[12];
    const float* ln2_b  = (const float*)d_in[13];
    const float* fc1_w  = (const float*)d_in[14];
    const float* fc1_b  = (const float*)d_in[15];
    const float* fc1_la = (const float*)d_in[16];
    const float* fc1_lb = (const float*)d_in[17];
    const float* fc2_w  = (const float*)d_in[18];
    const float* fc2_b  = (const float*)d_in[19];
    const float* fc2_la = (const float*)d_in[20];
    const float* fc2_lb = (const float*)d_in[21];
    float* out = (float*)d_out;

    float *wqkv, *wproj, *wfc1, *wfc2, *xw, *qkv, *attn, *x2, *xn2, *hb;
    cudaGetSymbolAddress((void**)&wqkv,  g_wqkv);
    cudaGetSymbolAddress((void**)&wproj, g_wproj);
    cudaGetSymbolAddress((void**)&wfc1,  g_wfc1);
    cudaGetSymbolAddress((void**)&wfc2,  g_wfc2);
    cudaGetSymbolAddress((void**)&xw,    g_xw);
    cudaGetSymbolAddress((void**)&qkv,   g_qkv);
    cudaGetSymbolAddress((void**)&attn,  g_attn);
    cudaGetSymbolAddress((void**)&x2,    g_x2);
    cudaGetSymbolAddress((void**)&xn2,   g_xn2);
    cudaGetSymbolAddress((void**)&hb,    g_hbuf);

    // 1) fold LoRA into (transposed) weights
    {
        int n1 = C3 * CH, n2 = CH * CH, n3 = FF * CH, n4 = CH * FF;
        fuse_w_kernel<<<(n1 + 255) / 256, 256>>>(qkv_w,  qkv_la,  qkv_lb,  wqkv,  C3, CH);
        fuse_w_kernel<<<(n2 + 255) / 256, 256>>>(proj_w, proj_la, proj_lb, wproj, CH, CH);
        fuse_w_kernel<<<(n3 + 255) / 256, 256>>>(fc1_w,  fc1_la,  fc1_lb,  wfc1,  FF, CH);
        fuse_w_kernel<<<(n4 + 255) / 256, 256>>>(fc2_w,  fc2_la,  fc2_lb,  wfc2,  CH, FF);
    }

    // 2) LN1 + cyclic shift + window partition
    ln_kernel<true><<<TOK, 256>>>(x, ln1_s, ln1_b, xw);

    // 3) QKV GEMM
    {
        dim3 grid(C3 / BN, TOK / BM);
        sgemm128<0><<<grid, 256>>>(xw, wqkv, qkv_b, nullptr, qkv, TOK, C3, CH);
    }

    // 4) windowed attention (rel-pos bias + shift mask + softmax)
    attn_kernel<<<dim3(NWIN, NHD), 256>>>(rpb);

    // 5) proj GEMM + window reverse + reverse shift + residual (-> natural order x2)
    {
        dim3 grid(CH / BN, TOK / BM);
        sgemm128<2><<<grid, 256>>>(attn, wproj, proj_b, x, x2, TOK, CH, CH);
    }

    // 6) LN2
    ln_kernel<false><<<TOK, 256>>>(x2, ln2_s, ln2_b, xn2);

    // 7) fc1 + GELU
    {
        dim3 grid(FF / BN, TOK / BM);
        sgemm128<1><<<grid, 256>>>(xn2, wfc1, fc1_b, nullptr, hb, TOK, FF, CH);
    }

    // 8) fc2 + residual -> out
    {
        dim3 grid(CH / BN, TOK / BM);
        sgemm128<3><<<grid, 256>>>(hb, wfc2, fc2_b, x2, out, TOK, CH, FF);
    }
}

// round 2
// speedup vs baseline: 3.0253x; 3.0253x over previous
#include <cuda_runtime.h>
#include <math.h>
#include <stdint.h>

// ---------------- problem constants ----------------
#define TOK   50176          // 64 * 784  (= 1024 windows * 49)
#define CH    512
#define C3    1536
#define FF    2048
#define NHD   16
#define HD    32
#define NWIN  1024
#define NTOKW 49

// ---------------- device scratch ----------------
__device__ float g_wqkv[CH * C3];     // K-major effective qkv weight  [K][N] (tf32)
__device__ float g_wproj[CH * CH];
__device__ float g_wfc1[CH * FF];
__device__ float g_wfc2[FF * CH];
__device__ float g_xw  [(size_t)TOK * CH];   // LN1 + shift + window-partitioned (tf32)
__device__ float g_qkv [(size_t)TOK * C3];   // fp32
__device__ float g_attn[(size_t)TOK * CH];   // attention output, windowed order (tf32)
__device__ float g_x2  [(size_t)TOK * CH];   // residual 1, natural order (fp32)
__device__ float g_xn2 [(size_t)TOK * CH];   // LN2 out (tf32)
__device__ float g_hbuf[(size_t)TOK * FF];   // fc1+gelu out (tf32)

// ---------------- helpers ----------------
__device__ __forceinline__ float to_tf32(float x) {
    uint32_t u; asm("cvt.rna.tf32.f32 %0, %1;" : "=r"(u) : "f"(x));
    return __uint_as_float(u);
}

__device__ __forceinline__ void mma_tf32(float c[4],
        uint32_t a0, uint32_t a1, uint32_t a2, uint32_t a3,
        uint32_t b0, uint32_t b1) {
    asm volatile("mma.sync.aligned.m16n8k8.row.col.f32.tf32.tf32.f32 "
        "{%0,%1,%2,%3}, {%4,%5,%6,%7}, {%8,%9}, {%0,%1,%2,%3};"
        : "+f"(c[0]), "+f"(c[1]), "+f"(c[2]), "+f"(c[3])
        : "r"(a0), "r"(a1), "r"(a2), "r"(a3), "r"(b0), "r"(b1));
}

__device__ __forceinline__ void cp16(void* smem, const void* g) {
    uint32_t s = (uint32_t)__cvta_generic_to_shared(smem);
    asm volatile("cp.async.ca.shared.global [%0], [%1], 16;" :: "r"(s), "l"(g));
}
__device__ __forceinline__ void cp_commit() { asm volatile("cp.async.commit_group;"); }
__device__ __forceinline__ void cp_wait1()  { asm volatile("cp.async.wait_group 1;"); }

__device__ __forceinline__ float gelu_exact(float x) {
    return 0.5f * x * (1.0f + erff(x * 0.70710678118654752f));
}

// ---------------- weight fusion (coalesced transpose + LoRA), tf32 out ----------------
// Wt[k][n] = W[n][k] + sum_r lb[n][r]*la[r][k]
__global__ void fuse_w_kernel(const float* __restrict__ W, const float* __restrict__ la,
                              const float* __restrict__ lb, float* __restrict__ Wt,
                              int N, int K) {
    __shared__ float tile[32][33];
    __shared__ float slb[32][17];
    int tx = threadIdx.x, ty = threadIdx.y;
    int bk = blockIdx.x * 32, bn = blockIdx.y * 32;
    for (int i = ty; i < 32; i += 8)
        tile[i][tx] = W[(size_t)(bn + i) * K + bk + tx];
    int t = ty * 32 + tx;
    for (int u = t; u < 512; u += 256)
        slb[u >> 4][u & 15] = lb[(size_t)(bn + (u >> 4)) * 16 + (u & 15)];
    __syncthreads();
    for (int i = ty; i < 32; i += 8) {
        float acc = tile[tx][i];
#pragma unroll
        for (int r = 0; r < 16; r++)
            acc += slb[tx][r] * la[(size_t)r * K + bk + i];
        Wt[(size_t)(bk + i) * N + bn + tx] = to_tf32(acc);
    }
}

// ---------------- layernorm (optional shift + window-partition gather), tf32 out ----------------
template <bool GATHER>
__global__ void ln_kernel(const float* __restrict__ x, const float* __restrict__ s,
                          const float* __restrict__ b, float* __restrict__ out) {
    int t = blockIdx.x;
    const float* row;
    if (GATHER) {
        int wnd = t / NTOKW, n = t - wnd * NTOKW;
        int bb = wnd >> 4, wl = wnd & 15;
        int wh = wl >> 2, ww = wl & 3;
        int i = n / 7, j = n - i * 7;
        int hs = wh * 7 + i, ws = ww * 7 + j;
        int h = hs + 3; if (h >= 28) h -= 28;
        int wc = ws + 3; if (wc >= 28) wc -= 28;
        row = x + ((size_t)bb * 784 + h * 28 + wc) * CH;
    } else {
        row = x + (size_t)t * CH;
    }
    int tid = threadIdx.x;
    float v0 = row[tid], v1 = row[tid + 256];
    float sum = v0 + v1, sq = v0 * v0 + v1 * v1;
#pragma unroll
    for (int o = 16; o > 0; o >>= 1) {
        sum += __shfl_xor_sync(0xffffffffu, sum, o);
        sq  += __shfl_xor_sync(0xffffffffu, sq, o);
    }
    __shared__ float ssum[8], ssq[8];
    if ((tid & 31) == 0) { ssum[tid >> 5] = sum; ssq[tid >> 5] = sq; }
    __syncthreads();
    float tsum = 0.f, tsq = 0.f;
#pragma unroll
    for (int i = 0; i < 8; i++) { tsum += ssum[i]; tsq += ssq[i]; }
    float mean = tsum * (1.f / CH);
    float var  = tsq * (1.f / CH) - mean * mean;
    float rstd = rsqrtf(var + 1e-5f);
    float* orow = out + (size_t)t * CH;
    orow[tid]       = to_tf32((v0 - mean) * rstd * s[tid]       + b[tid]);
    orow[tid + 256] = to_tf32((v1 - mean) * rstd * s[tid + 256] + b[tid + 256]);
}

// ---------------- windowed attention on tensor cores ----------------
// one block per (window, head), 128 threads = 4 warps, warp w owns m-tile w (16 rows)
__global__ __launch_bounds__(128) void attn_kernel(const float* __restrict__ rpb) {
    int w = blockIdx.x, hh = blockIdx.y;
    __shared__ float Qs[64][36];
    __shared__ float Ks[56][36];
    __shared__ float Vs[56][40];
    __shared__ float sc[64][57];
    __shared__ int   regid[49];
    int tid = threadIdx.x;
    int lane = tid & 31, warp = tid >> 5;
    int gid = lane >> 2, tig = lane & 3;

    // zero smem (pads must be finite / zero)
    for (int i = tid; i < 64 * 36; i += 128) ((float*)Qs)[i] = 0.f;
    for (int i = tid; i < 56 * 36; i += 128) ((float*)Ks)[i] = 0.f;
    for (int i = tid; i < 56 * 40; i += 128) ((float*)Vs)[i] = 0.f;
    __syncthreads();

    size_t base = (size_t)w * 49 * C3 + (size_t)hh * HD;
    for (int idx = tid; idx < 49 * 8; idx += 128) {
        int n = idx >> 3, dq = (idx & 7) * 4;
        const float4 q4 = *(const float4*)&g_qkv[base + (size_t)n * C3 + dq];
        const float4 k4 = *(const float4*)&g_qkv[base + (size_t)n * C3 + 512 + dq];
        const float4 v4 = *(const float4*)&g_qkv[base + (size_t)n * C3 + 1024 + dq];
        Qs[n][dq]   = to_tf32(q4.x); Qs[n][dq+1] = to_tf32(q4.y);
        Qs[n][dq+2] = to_tf32(q4.z); Qs[n][dq+3] = to_tf32(q4.w);
        Ks[n][dq]   = to_tf32(k4.x); Ks[n][dq+1] = to_tf32(k4.y);
        Ks[n][dq+2] = to_tf32(k4.z); Ks[n][dq+3] = to_tf32(k4.w);
        Vs[n][dq]   = to_tf32(v4.x); Vs[n][dq+1] = to_tf32(v4.y);
        Vs[n][dq+2] = to_tf32(v4.z); Vs[n][dq+3] = to_tf32(v4.w);
    }
    if (tid < 49) {
        int wl = w & 15, wh = wl >> 2, ww = wl & 3;
        int i = tid / 7, j = tid - i * 7;
        int hs = wh * 7 + i, ws = ww * 7 + j;
        int rh = hs < 21 ? 0 : (hs < 25 ? 1 : 2);
        int rw = ws < 21 ? 0 : (ws < 25 ? 1 : 2);
        regid[tid] = rh * 3 + rw;
    }
    __syncthreads();

    // S = Q * K^T   (warp handles rows [warp*16, warp*16+16), 7 n-tiles, 4 k-steps)
    {
        float c[7][4];
#pragma unroll
        for (int nt = 0; nt < 7; nt++)
#pragma unroll
            for (int i = 0; i < 4; i++) c[nt][i] = 0.f;
#pragma unroll
        for (int kk = 0; kk < 4; kk++) {
            int r = warp * 16 + gid;
            uint32_t a0 = __float_as_uint(Qs[r][kk*8+tig]);
            uint32_t a1 = __float_as_uint(Qs[r+8][kk*8+tig]);
            uint32_t a2 = __float_as_uint(Qs[r][kk*8+tig+4]);
            uint32_t a3 = __float_as_uint(Qs[r+8][kk*8+tig+4]);
#pragma unroll
            for (int nt = 0; nt < 7; nt++) {
                uint32_t b0 = __float_as_uint(Ks[nt*8+gid][kk*8+tig]);
                uint32_t b1 = __float_as_uint(Ks[nt*8+gid][kk*8+tig+4]);
                mma_tf32(c[nt], a0, a1, a2, a3, b0, b1);
            }
        }
#pragma unroll
        for (int nt = 0; nt < 7; nt++) {
            int r = warp * 16 + gid, cc = nt * 8 + 2 * tig;
            sc[r][cc]     = c[nt][0]; sc[r][cc+1]   = c[nt][1];
            sc[r+8][cc]   = c[nt][2]; sc[r+8][cc+1] = c[nt][3];
        }
    }
    __syncthreads();

    // scale + rel-pos bias + shift mask; zero pad cols 49..55
    const float scale = 0.1767766952966369f;   // 32^-0.5
    for (int idx = tid; idx < 49 * 49; idx += 128) {
        int n = idx / 49, m = idx - n * 49;
        int i1 = n / 7, j1 = n - i1 * 7;
        int i2 = m / 7, j2 = m - i2 * 7;
        float bias = rpb[((i1 - i2 + 6) * 13 + (j1 - j2 + 6)) * NHD + hh];
        float mv = (regid[n] != regid[m]) ? -100.f : 0.f;
        sc[n][m] = sc[n][m] * scale + bias + mv;
    }
    for (int idx = tid; idx < 64 * 7; idx += 128)
        sc[idx / 7][49 + idx % 7] = 0.f;
    __syncthreads();

    // softmax (rows 0..48), P rounded to tf32
    if (tid < 49) {
        float mx = -1e30f;
        for (int m = 0; m < 49; m++) mx = fmaxf(mx, sc[tid][m]);
        float s = 0.f;
        for (int m = 0; m < 49; m++) { float e = __expf(sc[tid][m] - mx); sc[tid][m] = e; s += e; }
        float inv = 1.f / s;
        for (int m = 0; m < 49; m++) sc[tid][m] = to_tf32(sc[tid][m] * inv);
    }
    __syncthreads();

    // O = P * V   (4 n-tiles over d, 7 k-steps over m)
    {
        float c[4][4];
#pragma unroll
        for (int nt = 0; nt < 4; nt++)
#pragma unroll
            for (int i = 0; i < 4; i++) c[nt][i] = 0.f;
#pragma unroll
        for (int kk = 0; kk < 7; kk++) {
            int r = warp * 16 + gid;
            uint32_t a0 = __float_as_uint(sc[r][kk*8+tig]);
            uint32_t a1 = __float_as_uint(sc[r+8][kk*8+tig]);
            uint32_t a2 = __float_as_uint(sc[r][kk*8+tig+4]);
            uint32_t a3 = __float_as_uint(sc[r+8][kk*8+tig+4]);
#pragma unroll
            for (int nt = 0; nt < 4; nt++) {
                uint32_t b0 = __float_as_uint(Vs[kk*8+tig][nt*8+gid]);
                uint32_t b1 = __float_as_uint(Vs[kk*8+tig+4][nt*8+gid]);
                mma_tf32(c[nt], a0, a1, a2, a3, b0, b1);
            }
        }
        int r = warp * 16 + gid;
#pragma unroll
        for (int half = 0; half < 2; half++) {
            int n = r + half * 8;
            if (n < 49) {
                size_t orow = ((size_t)w * 49 + n) * CH + hh * HD;
#pragma unroll
                for (int nt = 0; nt < 4; nt++) {
                    int d = nt * 8 + 2 * tig;
                    float2 v;
                    v.x = to_tf32(c[nt][half * 2 + 0]);
                    v.y = to_tf32(c[nt][half * 2 + 1]);
                    *(float2*)&g_attn[orow + d] = v;
                }
            }
        }
    }
}

// ---------------- tf32 tensor-core GEMM: C[M,N] = A[M,K] * Bt[K,N] + bias ----------------
// EPI: 0 bias, 1 bias+GELU(tf32 out), 2 proj (scatter + residual), 3 bias + residual
template <int EPI>
__global__ __launch_bounds__(256)
void gemm_tc(const float* __restrict__ A, const float* __restrict__ Bt,
             const float* __restrict__ bias, const float* __restrict__ res,
             float* __restrict__ C, int M, int N, int K) {
    __shared__ float As[2][128][20];
    __shared__ float Bs[2][16][132];
    int tid = threadIdx.x;
    int lane = tid & 31, warp = tid >> 5;
    int wm = (warp >> 2) * 64, wn = (warp & 3) * 32;
    int gid = lane >> 2, tig = lane & 3;
    int bm = blockIdx.y * 128, bn = blockIdx.x * 128;

    float acc[4][4][4];
#pragma unroll
    for (int i = 0; i < 4; i++)
#pragma unroll
        for (int j = 0; j < 4; j++)
#pragma unroll
            for (int k = 0; k < 4; k++) acc[i][j][k] = 0.f;

    int arow = tid >> 2, acol = (tid & 3) * 4;
    int brow = tid >> 5, bcol = lane * 4;
    const float* abase = A + (size_t)(bm + arow) * K + acol;
    const float* bbase = Bt + (size_t)brow * N + bn + bcol;

    int NIT = K >> 4;
    // stage 0
    {
        cp16(&As[0][arow][acol], abase);
        cp16(&As[0][arow + 64][acol], abase + (size_t)64 * K);
        cp16(&Bs[0][brow][bcol], bbase);
        cp16(&Bs[0][brow + 8][bcol], bbase + (size_t)8 * N);
        cp_commit();
    }
    for (int it = 0; it < NIT; ++it) {
        if (it + 1 < NIT) {
            int buf = (it + 1) & 1;
            const float* ap = abase + (it + 1) * 16;
            const float* bp = bbase + (size_t)(it + 1) * 16 * N;
            cp16(&As[buf][arow][acol], ap);
            cp16(&As[buf][arow + 64][acol], ap + (size_t)64 * K);
            cp16(&Bs[buf][brow][bcol], bp);
            cp16(&Bs[buf][brow + 8][bcol], bp + (size_t)8 * N);
        }
        cp_commit();
        cp_wait1();
        __syncthreads();
        int buf = it & 1;
#pragma unroll
        for (int kk = 0; kk < 2; kk++) {
            uint32_t a[4][4], b[4][2];
#pragma unroll
            for (int mt = 0; mt < 4; mt++) {
                int r = wm + mt * 16 + gid;
                a[mt][0] = __float_as_uint(As[buf][r][kk*8+tig]);
                a[mt][1] = __float_as_uint(As[buf][r+8][kk*8+tig]);
                a[mt][2] = __float_as_uint(As[buf][r][kk*8+tig+4]);
                a[mt][3] = __float_as_uint(As[buf][r+8][kk*8+tig+4]);
            }
#pragma unroll
            for (int nt = 0; nt < 4; nt++) {
                int c = wn + nt * 8 + gid;
                b[nt][0] = __float_as_uint(Bs[buf][kk*8+tig][c]);
                b[nt][1] = __float_as_uint(Bs[buf][kk*8+tig+4][c]);
            }
#pragma unroll
            for (int mt = 0; mt < 4; mt++)
#pragma unroll
                for (int nt = 0; nt < 4; nt++)
                    mma_tf32(acc[mt][nt], a[mt][0], a[mt][1], a[mt][2], a[mt][3],
                             b[nt][0], b[nt][1]);
        }
        __syncthreads();
    }

    // epilogue
#pragma unroll
    for (int mt = 0; mt < 4; mt++) {
#pragma unroll
        for (int half = 0; half < 2; half++) {
            int m = bm + wm + mt * 16 + gid + half * 8;
            size_t drow;
            if (EPI == 2) {
                int wnd = m / 49, n = m - wnd * 49;
                int bb = wnd >> 4, wl = wnd & 15;
                int wh = wl >> 2, ww = wl & 3;
                int ii = n / 7, jj = n - ii * 7;
                int h_ = wh * 7 + ii + 3; if (h_ >= 28) h_ -= 28;
                int w_ = ww * 7 + jj + 3; if (w_ >= 28) w_ -= 28;
                drow = (size_t)(bb * 784 + h_ * 28 + w_);
            } else {
                drow = (size_t)m;
            }
#pragma unroll
            for (int nt = 0; nt < 4; nt++) {
                int cc = bn + wn + nt * 8 + 2 * tig;
                float v0 = acc[mt][nt][half * 2 + 0] + bias[cc];
                float v1 = acc[mt][nt][half * 2 + 1] + bias[cc + 1];
                if (EPI == 1) { v0 = to_tf32(gelu_exact(v0)); v1 = to_tf32(gelu_exact(v1)); }
                if (EPI == 2) { v0 += res[drow * N + cc]; v1 += res[drow * N + cc + 1]; }
                if (EPI == 3) { v0 += res[(size_t)m * N + cc]; v1 += res[(size_t)m * N + cc + 1]; }
                float2 o; o.x = v0; o.y = v1;
                *(float2*)&C[drow * N + cc] = o;
            }
        }
    }
}

// ---------------- launch ----------------
extern "C" void kernel_launch(void* const* d_in, const int* in_sizes, int n_in,
                              void* d_out, int out_size) {
    const float* x      = (const float*)d_in[0];
    const float* ln1_s  = (const float*)d_in[1];
    const float* ln1_b  = (const float*)d_in[2];
    const float* qkv_w  = (const float*)d_in[3];
    const float* qkv_b  = (const float*)d_in[4];
    const float* qkv_la = (const float*)d_in[5];
    const float* qkv_lb = (const float*)d_in[6];
    const float* rpb    = (const float*)d_in[7];
    const float* proj_w = (const float*)d_in[8];
    const float* proj_b = (const float*)d_in[9];
    const float* proj_la= (const float*)d_in[10];
    const float* proj_lb= (const float*)d_in[11];
    const float* ln2_s  = (const float*)d_in[12];
    const float* ln2_b  = (const float*)d_in[13];
    const float* fc1_w  = (const float*)d_in[14];
    const float* fc1_b  = (const float*)d_in[15];
    const float* fc1_la = (const float*)d_in[16];
    const float* fc1_lb = (const float*)d_in[17];
    const float* fc2_w  = (const float*)d_in[18];
    const float* fc2_b  = (const float*)d_in[19];
    const float* fc2_la = (const float*)d_in[20];
    const float* fc2_lb = (const float*)d_in[21];
    float* out = (float*)d_out;

    float *wqkv, *wproj, *wfc1, *wfc2, *xw, *qkv, *attn, *x2, *xn2, *hb;
    cudaGetSymbolAddress((void**)&wqkv,  g_wqkv);
    cudaGetSymbolAddress((void**)&wproj, g_wproj);
    cudaGetSymbolAddress((void**)&wfc1,  g_wfc1);
    cudaGetSymbolAddress((void**)&wfc2,  g_wfc2);
    cudaGetSymbolAddress((void**)&xw,    g_xw);
    cudaGetSymbolAddress((void**)&qkv,   g_qkv);
    cudaGetSymbolAddress((void**)&attn,  g_attn);
    cudaGetSymbolAddress((void**)&x2,    g_x2);
    cudaGetSymbolAddress((void**)&xn2,   g_xn2);
    cudaGetSymbolAddress((void**)&hb,    g_hbuf);

    // 1) fold LoRA into transposed weights (tf32)
    fuse_w_kernel<<<dim3(CH / 32, C3 / 32), dim3(32, 8)>>>(qkv_w,  qkv_la,  qkv_lb,  wqkv,  C3, CH);
    fuse_w_kernel<<<dim3(CH / 32, CH / 32), dim3(32, 8)>>>(proj_w, proj_la, proj_lb, wproj, CH, CH);
    fuse_w_kernel<<<dim3(CH / 32, FF / 32), dim3(32, 8)>>>(fc1_w,  fc1_la,  fc1_lb,  wfc1,  FF, CH);
    fuse_w_kernel<<<dim3(FF / 32, CH / 32), dim3(32, 8)>>>(fc2_w,  fc2_la,  fc2_lb,  wfc2,  CH, FF);

    // 2) LN1 + shift + window partition
    ln_kernel<true><<<TOK, 256>>>(x, ln1_s, ln1_b, xw);

    // 3) QKV GEMM
    gemm_tc<0><<<dim3(C3 / 128, TOK / 128), 256>>>(xw, wqkv, qkv_b, nullptr, qkv, TOK, C3, CH);

    // 4) windowed attention (tensor-core S and PV)
    attn_kernel<<<dim3(NWIN, NHD), 128>>>(rpb);

    // 5) proj GEMM + window reverse + reverse shift + residual
    gemm_tc<2><<<dim3(CH / 128, TOK / 128), 256>>>(attn, wproj, proj_b, x, x2, TOK, CH, CH);

    // 6) LN2
    ln_kernel<false><<<TOK, 256>>>(x2, ln2_s, ln2_b, xn2);

    // 7) fc1 + GELU
    gemm_tc<1><<<dim3(FF / 128, TOK / 128), 256>>>(xn2, wfc1, fc1_b, nullptr, hb, TOK, FF, CH);

    // 8) fc2 + residual -> out
    gemm_tc<3><<<dim3(CH / 128, TOK / 128), 256>>>(hb, wfc2, fc2_b, x2, out, TOK, CH, FF);
}

// round 4
// speedup vs baseline: 5.0649x; 1.6742x over previous
#include <cuda_runtime.h>
#include <cuda_fp16.h>
#include <math.h>
#include <stdint.h>

// ---------------- problem constants ----------------
#define TOK   50176
#define CH    512
#define C3    1536
#define FF    2048
#define NHD   16
#define HD    32
#define NWIN  1024

// ---------------- device scratch ----------------
__device__ __half g_wqkv[C3 * CH];            // effective weights, [N][K] K-major
__device__ __half g_wproj[CH * CH];
__device__ __half g_wfc1[FF * CH];
__device__ __half g_wfc2[CH * FF];
__device__ __half g_xw  [(size_t)TOK * CH];   // LN1 + shift + window-partitioned
__device__ __half g_qkv [(size_t)TOK * C3];
__device__ __half g_attn[(size_t)TOK * CH];   // attention out, windowed order
__device__ float  g_x2  [(size_t)TOK * CH];   // residual 1, natural order (fp32)
__device__ __half g_xn2 [(size_t)TOK * CH];
__device__ __half g_hbuf[(size_t)TOK * FF];

// ---------------- helpers ----------------
__device__ __forceinline__ float gelu_exact(float x) {
    return 0.5f * x * (1.0f + erff(x * 0.70710678118654752f));
}
__device__ __forceinline__ void cp16(const void* smem, const void* g) {
    uint32_t s = (uint32_t)__cvta_generic_to_shared(smem);
    asm volatile("cp.async.ca.shared.global [%0], [%1], 16;" :: "r"(s), "l"(g));
}
__device__ __forceinline__ void cp_commit() { asm volatile("cp.async.commit_group;"); }
__device__ __forceinline__ void cp_wait1()  { asm volatile("cp.async.wait_group 1;"); }

__device__ __forceinline__ void mma16816(float c[4],
        uint32_t a0, uint32_t a1, uint32_t a2, uint32_t a3,
        uint32_t b0, uint32_t b1) {
    asm volatile("mma.sync.aligned.m16n8k16.row.col.f32.f16.f16.f32 "
        "{%0,%1,%2,%3}, {%4,%5,%6,%7}, {%8,%9}, {%0,%1,%2,%3};"
        : "+f"(c[0]), "+f"(c[1]), "+f"(c[2]), "+f"(c[3])
        : "r"(a0), "r"(a1), "r"(a2), "r"(a3), "r"(b0), "r"(b1));
}

// ---------------- weight fusion: Wh[n][k] = W[n][k] + sum_r lb[n][r]*la[r][k] ----------------
__global__ void fuse_w_kernel(const float* __restrict__ W, const float* __restrict__ la,
                              const float* __restrict__ lb, __half* __restrict__ Wh,
                              int N, int K) {
    int idx = blockIdx.x * blockDim.x + threadIdx.x;
    if (idx >= N * K) return;
    int n = idx / K, k = idx - n * K;
    float acc = W[idx];
#pragma unroll
    for (int r = 0; r < 16; r++) acc += lb[n * 16 + r] * la[(size_t)r * K + k];
    Wh[idx] = __float2half(acc);
}

// ---------------- layernorm (optional shift + window gather), half out ----------------
template <bool GATHER>
__global__ void ln_kernel(const float* __restrict__ x, const float* __restrict__ s,
                          const float* __restrict__ b, __half* __restrict__ out) {
    int t = blockIdx.x;
    const float* row;
    if (GATHER) {
        int wnd = t / 49, n = t - wnd * 49;
        int bb = wnd >> 4, wl = wnd & 15;
        int wh = wl >> 2, ww = wl & 3;
        int i = n / 7, j = n - i * 7;
        int h = wh * 7 + i + 3; if (h >= 28) h -= 28;
        int wc = ww * 7 + j + 3; if (wc >= 28) wc -= 28;
        row = x + ((size_t)bb * 784 + h * 28 + wc) * CH;
    } else {
        row = x + (size_t)t * CH;
    }
    int tid = threadIdx.x;
    float v0 = row[tid], v1 = row[tid + 256];
    float sum = v0 + v1, sq = v0 * v0 + v1 * v1;
#pragma unroll
    for (int o = 16; o > 0; o >>= 1) {
        sum += __shfl_xor_sync(0xffffffffu, sum, o);
        sq  += __shfl_xor_sync(0xffffffffu, sq, o);
    }
    __shared__ float ssum[8], ssq[8];
    if ((tid & 31) == 0) { ssum[tid >> 5] = sum; ssq[tid >> 5] = sq; }
    __syncthreads();
    float tsum = 0.f, tsq = 0.f;
#pragma unroll
    for (int i = 0; i < 8; i++) { tsum += ssum[i]; tsq += ssq[i]; }
    float mean = tsum * (1.f / CH);
    float var  = tsq * (1.f / CH) - mean * mean;
    float rstd = rsqrtf(var + 1e-5f);
    __half* orow = out + (size_t)t * CH;
    orow[tid]       = __float2half((v0 - mean) * rstd * s[tid]       + b[tid]);
    orow[tid + 256] = __float2half((v1 - mean) * rstd * s[tid + 256] + b[tid + 256]);
}

// ---------------- windowed attention, fp16 mma ----------------
// one block per (window, head), 128 threads = 4 warps; warp w owns rows [w*16, w*16+16)
__global__ __launch_bounds__(128) void attn_kernel(const float* __restrict__ rpb) {
    __shared__ __half Qs[64][40];
    __shared__ __half Ks[56][40];
    __shared__ __half Vt[32][72];   // V transposed: [d][m]
    __shared__ __half Ps[64][72];   // softmax probs (A operand of PV)
    __shared__ float  sc[64][57];
    __shared__ int    regid[49];
    int w = blockIdx.x, hh = blockIdx.y;
    int tid = threadIdx.x;
    int lane = tid & 31, warp = tid >> 5;
    int gid = lane >> 2, tig = lane & 3;

    for (int i = tid; i < 64 * 40 / 2; i += 128) ((uint32_t*)Qs)[i] = 0;
    for (int i = tid; i < 56 * 40 / 2; i += 128) ((uint32_t*)Ks)[i] = 0;
    for (int i = tid; i < 32 * 72 / 2; i += 128) ((uint32_t*)Vt)[i] = 0;
    for (int i = tid; i < 64 * 72 / 2; i += 128) ((uint32_t*)Ps)[i] = 0;
    __syncthreads();

    size_t base = (size_t)w * 49 * C3 + (size_t)hh * HD;
    for (int idx = tid; idx < 49 * 4; idx += 128) {
        int n = idx >> 2, dq = (idx & 3) * 8;
        uint4 q4 = *(const uint4*)&g_qkv[base + (size_t)n * C3 + dq];
        uint4 k4 = *(const uint4*)&g_qkv[base + (size_t)n * C3 + 512 + dq];
        uint4 v4 = *(const uint4*)&g_qkv[base + (size_t)n * C3 + 1024 + dq];
        *(uint4*)&Qs[n][dq] = q4;
        *(uint4*)&Ks[n][dq] = k4;
        // transpose V into Vt[d][m]
        uint32_t vp[4] = {v4.x, v4.y, v4.z, v4.w};
#pragma unroll
        for (int p = 0; p < 4; p++) {
            __half2 h2 = *(__half2*)&vp[p];
            Vt[dq + p * 2 + 0][n] = __low2half(h2);
            Vt[dq + p * 2 + 1][n] = __high2half(h2);
        }
    }
    if (tid < 49) {
        int wl = w & 15, wh = wl >> 2, ww = wl & 3;
        int i = tid / 7, j = tid - i * 7;
        int hs = wh * 7 + i, ws = ww * 7 + j;
        int rh = hs < 21 ? 0 : (hs < 25 ? 1 : 2);
        int rw = ws < 21 ? 0 : (ws < 25 ? 1 : 2);
        regid[tid] = rh * 3 + rw;
    }
    __syncthreads();

    // S = Q * K^T : rows warp*16..+15, 7 n-tiles, 2 k-steps of 16
    {
        float c[7][4];
#pragma unroll
        for (int nt = 0; nt < 7; nt++)
#pragma unroll
            for (int i = 0; i < 4; i++) c[nt][i] = 0.f;
        int r = warp * 16 + gid;
#pragma unroll
        for (int kk = 0; kk < 2; kk++) {
            int col = kk * 16 + tig * 2;
            uint32_t a0 = *(uint32_t*)&Qs[r][col];
            uint32_t a1 = *(uint32_t*)&Qs[r + 8][col];
            uint32_t a2 = *(uint32_t*)&Qs[r][col + 8];
            uint32_t a3 = *(uint32_t*)&Qs[r + 8][col + 8];
#pragma unroll
            for (int nt = 0; nt < 7; nt++) {
                uint32_t b0 = *(uint32_t*)&Ks[nt * 8 + gid][col];
                uint32_t b1 = *(uint32_t*)&Ks[nt * 8 + gid][col + 8];
                mma16816(c[nt], a0, a1, a2, a3, b0, b1);
            }
        }
#pragma unroll
        for (int nt = 0; nt < 7; nt++) {
            int cc = nt * 8 + 2 * tig;
            sc[r][cc]     = c[nt][0]; sc[r][cc+1]   = c[nt][1];
            sc[r+8][cc]   = c[nt][2]; sc[r+8][cc+1] = c[nt][3];
        }
    }
    __syncthreads();

    // scale + bias + mask
    const float scale = 0.1767766952966369f;
    for (int idx = tid; idx < 49 * 49; idx += 128) {
        int n = idx / 49, m = idx - n * 49;
        int i1 = n / 7, j1 = n - i1 * 7;
        int i2 = m / 7, j2 = m - i2 * 7;
        float bias = rpb[((i1 - i2 + 6) * 13 + (j1 - j2 + 6)) * NHD + hh];
        float mv = (regid[n] != regid[m]) ? -100.f : 0.f;
        sc[n][m] = sc[n][m] * scale + bias + mv;
    }
    __syncthreads();

    // softmax: warp per row
    for (int r = warp; r < 49; r += 4) {
        float v0 = sc[r][lane < 49 ? lane : 0];
        if (lane >= 49) v0 = -1e30f;
        float v1 = (lane < 17) ? sc[r][32 + lane] : -1e30f;
        float mx = fmaxf(v0, v1);
#pragma unroll
        for (int o = 16; o > 0; o >>= 1) mx = fmaxf(mx, __shfl_xor_sync(0xffffffffu, mx, o));
        float e0 = (lane < 49) ? __expf(v0 - mx) : 0.f;
        float e1 = (lane < 17) ? __expf(v1 - mx) : 0.f;
        float s = e0 + e1;
#pragma unroll
        for (int o = 16; o > 0; o >>= 1) s += __shfl_xor_sync(0xffffffffu, s, o);
        float inv = 1.f / s;
        if (lane < 49) Ps[r][lane] = __float2half(e0 * inv);
        if (lane < 17) Ps[r][32 + lane] = __float2half(e1 * inv);
    }
    __syncthreads();

    // O = P * V : 4 n-tiles over d, 4 k-steps over m (padded to 64)
    {
        float c[4][4];
#pragma unroll
        for (int nt = 0; nt < 4; nt++)
#pragma unroll
            for (int i = 0; i < 4; i++) c[nt][i] = 0.f;
        int r = warp * 16 + gid;
#pragma unroll
        for (int kk = 0; kk < 4; kk++) {
            int col = kk * 16 + tig * 2;
            uint32_t a0 = *(uint32_t*)&Ps[r][col];
            uint32_t a1 = *(uint32_t*)&Ps[r + 8][col];
            uint32_t a2 = *(uint32_t*)&Ps[r][col + 8];
            uint32_t a3 = *(uint32_t*)&Ps[r + 8][col + 8];
#pragma unroll
            for (int nt = 0; nt < 4; nt++) {
                uint32_t b0 = *(uint32_t*)&Vt[nt * 8 + gid][col];
                uint32_t b1 = *(uint32_t*)&Vt[nt * 8 + gid][col + 8];
                mma16816(c[nt], a0, a1, a2, a3, b0, b1);
            }
        }
#pragma unroll
        for (int half_ = 0; half_ < 2; half_++) {
            int n = warp * 16 + gid + half_ * 8;
            if (n < 49) {
                size_t orow = ((size_t)w * 49 + n) * CH + hh * HD;
#pragma unroll
                for (int nt = 0; nt < 4; nt++) {
                    int d = nt * 8 + 2 * tig;
                    __half2 h2 = __floats2half2_rn(c[nt][half_ * 2 + 0], c[nt][half_ * 2 + 1]);
                    *(__half2*)&g_attn[orow + d] = h2;
                }
            }
        }
    }
}

// ---------------- fp16 tensor-core GEMM: C[M,N] = A[M,K] * B[N,K]^T + bias ----------------
// EPI: 0 bias (half out), 1 bias+GELU (half out), 2 proj scatter+residual (f32 out),
//      3 bias+residual (f32 out)
#define BM 128
#define BN 128
#define BK 32

template <int EPI>
__global__ __launch_bounds__(256, 2)
void gemm_h(const __half* __restrict__ A, const __half* __restrict__ B,
            const float* __restrict__ bias, const float* __restrict__ res,
            void* __restrict__ Cv, int M, int N, int K) {
    __shared__ __half As[2][BM][BK + 8];
    __shared__ __half Bs[2][BN][BK + 8];
    int tid = threadIdx.x;
    int lane = tid & 31, warp = tid >> 5;
    int wm = (warp >> 2) * 64, wn = (warp & 3) * 32;
    int gid = lane >> 2, tig = lane & 3;
    int bm = blockIdx.y * BM, bn = blockIdx.x * BN;

    float acc[4][4][4];
#pragma unroll
    for (int i = 0; i < 4; i++)
#pragma unroll
        for (int j = 0; j < 4; j++)
#pragma unroll
            for (int k = 0; k < 4; k++) acc[i][j][k] = 0.f;

    // stage loader: 512 16B chunks per operand, 2 per thread each
    int r0 = tid >> 2, c0 = (tid & 3) * 8;
    const __half* Abase = A + (size_t)(bm + r0) * K + c0;
    const __half* Bbase = B + (size_t)(bn + r0) * K + c0;

    int NIT = K / BK;
    {
        cp16(&As[0][r0][c0],      Abase);
        cp16(&As[0][r0 + 64][c0], Abase + (size_t)64 * K);
        cp16(&Bs[0][r0][c0],      Bbase);
        cp16(&Bs[0][r0 + 64][c0], Bbase + (size_t)64 * K);
        cp_commit();
    }
    for (int it = 0; it < NIT; ++it) {
        if (it + 1 < NIT) {
            int buf = (it + 1) & 1;
            const __half* ap = Abase + (it + 1) * BK;
            const __half* bp = Bbase + (it + 1) * BK;
            cp16(&As[buf][r0][c0],      ap);
            cp16(&As[buf][r0 + 64][c0], ap + (size_t)64 * K);
            cp16(&Bs[buf][r0][c0],      bp);
            cp16(&Bs[buf][r0 + 64][c0], bp + (size_t)64 * K);
        }
        cp_commit();
        cp_wait1();
        __syncthreads();
        int buf = it & 1;
#pragma unroll
        for (int kk = 0; kk < 2; kk++) {
            int col = kk * 16 + tig * 2;
            uint32_t a[4][4], b[4][2];
#pragma unroll
            for (int mt = 0; mt < 4; mt++) {
                int r = wm + mt * 16 + gid;
                a[mt][0] = *(uint32_t*)&As[buf][r][col];
                a[mt][1] = *(uint32_t*)&As[buf][r + 8][col];
                a[mt][2] = *(uint32_t*)&As[buf][r][col + 8];
                a[mt][3] = *(uint32_t*)&As[buf][r + 8][col + 8];
            }
#pragma unroll
            for (int nt = 0; nt < 4; nt++) {
                int n = wn + nt * 8 + gid;
                b[nt][0] = *(uint32_t*)&Bs[buf][n][col];
                b[nt][1] = *(uint32_t*)&Bs[buf][n][col + 8];
            }
#pragma unroll
            for (int mt = 0; mt < 4; mt++)
#pragma unroll
                for (int nt = 0; nt < 4; nt++)
                    mma16816(acc[mt][nt], a[mt][0], a[mt][1], a[mt][2], a[mt][3],
                             b[nt][0], b[nt][1]);
        }
        __syncthreads();
    }

    // epilogue
#pragma unroll
    for (int mt = 0; mt < 4; mt++) {
#pragma unroll
        for (int half_ = 0; half_ < 2; half_++) {
            int m = bm + wm + mt * 16 + gid + half_ * 8;
            size_t drow;
            if (EPI == 2) {
                int wnd = m / 49, n = m - wnd * 49;
                int bb = wnd >> 4, wl = wnd & 15;
                int wh = wl >> 2, ww = wl & 3;
                int ii = n / 7, jj = n - ii * 7;
                int h_ = wh * 7 + ii + 3; if (h_ >= 28) h_ -= 28;
                int w_ = ww * 7 + jj + 3; if (w_ >= 28) w_ -= 28;
                drow = (size_t)(bb * 784 + h_ * 28 + w_);
            } else {
                drow = (size_t)m;
            }
#pragma unroll
            for (int nt = 0; nt < 4; nt++) {
                int cc = bn + wn + nt * 8 + 2 * tig;
                float v0 = acc[mt][nt][half_ * 2 + 0] + bias[cc];
                float v1 = acc[mt][nt][half_ * 2 + 1] + bias[cc + 1];
                if (EPI == 1) { v0 = gelu_exact(v0); v1 = gelu_exact(v1); }
                if (EPI == 2 || EPI == 3) {
                    const float* rrow = res + drow * N;
                    v0 += rrow[cc]; v1 += rrow[cc + 1];
                    float2 o; o.x = v0; o.y = v1;
                    *(float2*)&((float*)Cv)[drow * N + cc] = o;
                } else {
                    __half2 h2 = __floats2half2_rn(v0, v1);
                    *(__half2*)&((__half*)Cv)[drow * N + cc] = h2;
                }
            }
        }
    }
}

// ---------------- launch ----------------
extern "C" void kernel_launch(void* const* d_in, const int* in_sizes, int n_in,
                              void* d_out, int out_size) {
    const float* x      = (const float*)d_in[0];
    const float* ln1_s  = (const float*)d_in[1];
    const float* ln1_b  = (const float*)d_in[2];
    const float* qkv_w  = (const float*)d_in[3];
    const float* qkv_b  = (const float*)d_in[4];
    const float* qkv_la = (const float*)d_in[5];
    const float* qkv_lb = (const float*)d_in[6];
    const float* rpb    = (const float*)d_in[7];
    const float* proj_w = (const float*)d_in[8];
    const float* proj_b = (const float*)d_in[9];
    const float* proj_la= (const float*)d_in[10];
    const float* proj_lb= (const float*)d_in[11];
    const float* ln2_s  = (const float*)d_in[12];
    const float* ln2_b  = (const float*)d_in[13];
    const float* fc1_w  = (const float*)d_in[14];
    const float* fc1_b  = (const float*)d_in[15];
    const float* fc1_la = (const float*)d_in[16];
    const float* fc1_lb = (const float*)d_in[17];
    const float* fc2_w  = (const float*)d_in[18];
    const float* fc2_b  = (const float*)d_in[19];
    const float* fc2_la = (const float*)d_in[20];
    const float* fc2_lb = (const float*)d_in[21];
    float* out = (float*)d_out;

    __half *wqkv, *wproj, *wfc1, *wfc2, *xw, *qkv, *attn, *xn2, *hb;
    float *x2;
    cudaGetSymbolAddress((void**)&wqkv,  g_wqkv);
    cudaGetSymbolAddress((void**)&wproj, g_wproj);
    cudaGetSymbolAddress((void**)&wfc1,  g_wfc1);
    cudaGetSymbolAddress((void**)&wfc2,  g_wfc2);
    cudaGetSymbolAddress((void**)&xw,    g_xw);
    cudaGetSymbolAddress((void**)&qkv,   g_qkv);
    cudaGetSymbolAddress((void**)&attn,  g_attn);
    cudaGetSymbolAddress((void**)&x2,    g_x2);
    cudaGetSymbolAddress((void**)&xn2,   g_xn2);
    cudaGetSymbolAddress((void**)&hb,    g_hbuf);

    // 1) fold LoRA into weights ([N][K], half)
    fuse_w_kernel<<<(C3 * CH + 255) / 256, 256>>>(qkv_w,  qkv_la,  qkv_lb,  wqkv,  C3, CH);
    fuse_w_kernel<<<(CH * CH + 255) / 256, 256>>>(proj_w, proj_la, proj_lb, wproj, CH, CH);
    fuse_w_kernel<<<(FF * CH + 255) / 256, 256>>>(fc1_w,  fc1_la,  fc1_lb,  wfc1,  FF, CH);
    fuse_w_kernel<<<(CH * FF + 255) / 256, 256>>>(fc2_w,  fc2_la,  fc2_lb,  wfc2,  CH, FF);

    // 2) LN1 + shift + window partition (half out)
    ln_kernel<true><<<TOK, 256>>>(x, ln1_s, ln1_b, xw);

    // 3) QKV GEMM (half out)
    gemm_h<0><<<dim3(C3 / BN, TOK / BM), 256>>>(xw, wqkv, qkv_b, nullptr, qkv, TOK, C3, CH);

    // 4) windowed attention (half out)
    attn_kernel<<<dim3(NWIN, NHD), 128>>>(rpb);

    // 5) proj GEMM + window reverse + reverse shift + residual (f32 out)
    gemm_h<2><<<dim3(CH / BN, TOK / BM), 256>>>(attn, wproj, proj_b, x, x2, TOK, CH, CH);

    // 6) LN2 (half out)
    ln_kernel<false><<<TOK, 256>>>(x2, ln2_s, ln2_b, xn2);

    // 7) fc1 + GELU (half out)
    gemm_h<1><<<dim3(FF / BN, TOK / BM), 256>>>(xn2, wfc1, fc1_b, nullptr, hb, TOK, FF, CH);

    // 8) fc2 + residual -> out (f32)
    gemm_h<3><<<dim3(CH / BN, TOK / BM), 256>>>(hb, wfc2, fc2_b, x2, out, TOK, CH, FF);
}

// round 5
// speedup vs baseline: 5.7166x; 1.1287x over previous
#include <cuda_runtime.h>
#include <cuda_fp16.h>
#include <math.h>
#include <stdint.h>

// ---------------- problem constants ----------------
#define TOK   50176
#define CH    512
#define C3    1536
#define FF    2048
#define NHD   16
#define HD    32
#define NWIN  1024

// ---------------- device scratch ----------------
__device__ __half g_wqkv[C3 * CH];            // effective weights, [N][K] K-major
__device__ __half g_wproj[CH * CH];
__device__ __half g_wfc1[FF * CH];
__device__ __half g_wfc2[CH * FF];
__device__ __half g_xw  [(size_t)TOK * CH];
__device__ __half g_qkv [(size_t)TOK * C3];
__device__ __half g_attn[(size_t)TOK * CH];
__device__ float  g_x2  [(size_t)TOK * CH];
__device__ __half g_xn2 [(size_t)TOK * CH];
__device__ __half g_hbuf[(size_t)TOK * FF];

// ---------------- helpers ----------------
__device__ __forceinline__ float gelu_exact(float x) {
    return 0.5f * x * (1.0f + erff(x * 0.70710678118654752f));
}
__device__ __forceinline__ void cp16(uint32_t saddr, const void* g) {
    asm volatile("cp.async.ca.shared.global [%0], [%1], 16;" :: "r"(saddr), "l"(g));
}
__device__ __forceinline__ void cp_commit() { asm volatile("cp.async.commit_group;"); }
__device__ __forceinline__ void cp_wait1()  { asm volatile("cp.async.wait_group 1;"); }

__device__ __forceinline__ void mma16816(float c[4],
        uint32_t a0, uint32_t a1, uint32_t a2, uint32_t a3,
        uint32_t b0, uint32_t b1) {
    asm volatile("mma.sync.aligned.m16n8k16.row.col.f32.f16.f16.f32 "
        "{%0,%1,%2,%3}, {%4,%5,%6,%7}, {%8,%9}, {%0,%1,%2,%3};"
        : "+f"(c[0]), "+f"(c[1]), "+f"(c[2]), "+f"(c[3])
        : "r"(a0), "r"(a1), "r"(a2), "r"(a3), "r"(b0), "r"(b1));
}
__device__ __forceinline__ void ldsm4(uint32_t* r, uint32_t addr) {
    asm volatile("ldmatrix.sync.aligned.m8n8.x4.shared.b16 {%0,%1,%2,%3}, [%4];"
        : "=r"(r[0]), "=r"(r[1]), "=r"(r[2]), "=r"(r[3]) : "r"(addr));
}

// ---------------- weight fusion ----------------
__global__ void fuse_w_kernel(const float* __restrict__ W, const float* __restrict__ la,
                              const float* __restrict__ lb, __half* __restrict__ Wh,
                              int N, int K) {
    int idx = blockIdx.x * blockDim.x + threadIdx.x;
    if (idx >= N * K) return;
    int n = idx / K, k = idx - n * K;
    float acc = W[idx];
#pragma unroll
    for (int r = 0; r < 16; r++) acc += lb[n * 16 + r] * la[(size_t)r * K + k];
    Wh[idx] = __float2half(acc);
}

// ---------------- layernorm (optional shift + window gather), half out ----------------
template <bool GATHER>
__global__ void ln_kernel(const float* __restrict__ x, const float* __restrict__ s,
                          const float* __restrict__ b, __half* __restrict__ out) {
    int t = blockIdx.x;
    const float* row;
    if (GATHER) {
        int wnd = t / 49, n = t - wnd * 49;
        int bb = wnd >> 4, wl = wnd & 15;
        int wh = wl >> 2, ww = wl & 3;
        int i = n / 7, j = n - i * 7;
        int h = wh * 7 + i + 3; if (h >= 28) h -= 28;
        int wc = ww * 7 + j + 3; if (wc >= 28) wc -= 28;
        row = x + ((size_t)bb * 784 + h * 28 + wc) * CH;
    } else {
        row = x + (size_t)t * CH;
    }
    int tid = threadIdx.x;
    float v0 = row[tid], v1 = row[tid + 256];
    float sum = v0 + v1, sq = v0 * v0 + v1 * v1;
#pragma unroll
    for (int o = 16; o > 0; o >>= 1) {
        sum += __shfl_xor_sync(0xffffffffu, sum, o);
        sq  += __shfl_xor_sync(0xffffffffu, sq, o);
    }
    __shared__ float ssum[8], ssq[8];
    if ((tid & 31) == 0) { ssum[tid >> 5] = sum; ssq[tid >> 5] = sq; }
    __syncthreads();
    float tsum = 0.f, tsq = 0.f;
#pragma unroll
    for (int i = 0; i < 8; i++) { tsum += ssum[i]; tsq += ssq[i]; }
    float mean = tsum * (1.f / CH);
    float var  = tsq * (1.f / CH) - mean * mean;
    float rstd = rsqrtf(var + 1e-5f);
    __half* orow = out + (size_t)t * CH;
    orow[tid]       = __float2half((v0 - mean) * rstd * s[tid]       + b[tid]);
    orow[tid + 256] = __float2half((v1 - mean) * rstd * s[tid + 256] + b[tid + 256]);
}

// ---------------- windowed attention, fp16 mma ----------------
__global__ __launch_bounds__(128) void attn_kernel(const float* __restrict__ rpb) {
    __shared__ __half Qs[64][40];
    __shared__ __half Ks[56][40];
    __shared__ __half Vt[32][72];
    __shared__ __half Ps[64][72];
    __shared__ float  sc[64][57];
    __shared__ int    regid[49];
    int w = blockIdx.x, hh = blockIdx.y;
    int tid = threadIdx.x;
    int lane = tid & 31, warp = tid >> 5;
    int gid = lane >> 2, tig = lane & 3;

    for (int i = tid; i < 64 * 40 / 2; i += 128) ((uint32_t*)Qs)[i] = 0;
    for (int i = tid; i < 56 * 40 / 2; i += 128) ((uint32_t*)Ks)[i] = 0;
    for (int i = tid; i < 32 * 72 / 2; i += 128) ((uint32_t*)Vt)[i] = 0;
    for (int i = tid; i < 64 * 72 / 2; i += 128) ((uint32_t*)Ps)[i] = 0;
    __syncthreads();

    size_t base = (size_t)w * 49 * C3 + (size_t)hh * HD;
    for (int idx = tid; idx < 49 * 4; idx += 128) {
        int n = idx >> 2, dq = (idx & 3) * 8;
        uint4 q4 = *(const uint4*)&g_qkv[base + (size_t)n * C3 + dq];
        uint4 k4 = *(const uint4*)&g_qkv[base + (size_t)n * C3 + 512 + dq];
        uint4 v4 = *(const uint4*)&g_qkv[base + (size_t)n * C3 + 1024 + dq];
        *(uint4*)&Qs[n][dq] = q4;
        *(uint4*)&Ks[n][dq] = k4;
        uint32_t vp[4] = {v4.x, v4.y, v4.z, v4.w};
#pragma unroll
        for (int p = 0; p < 4; p++) {
            __half2 h2 = *(__half2*)&vp[p];
            Vt[dq + p * 2 + 0][n] = __low2half(h2);
            Vt[dq + p * 2 + 1][n] = __high2half(h2);
        }
    }
    if (tid < 49) {
        int wl = w & 15, wh = wl >> 2, ww = wl & 3;
        int i = tid / 7, j = tid - i * 7;
        int hs = wh * 7 + i, ws = ww * 7 + j;
        int rh = hs < 21 ? 0 : (hs < 25 ? 1 : 2);
        int rw = ws < 21 ? 0 : (ws < 25 ? 1 : 2);
        regid[tid] = rh * 3 + rw;
    }
    __syncthreads();

    {
        float c[7][4];
#pragma unroll
        for (int nt = 0; nt < 7; nt++)
#pragma unroll
            for (int i = 0; i < 4; i++) c[nt][i] = 0.f;
        int r = warp * 16 + gid;
#pragma unroll
        for (int kk = 0; kk < 2; kk++) {
            int col = kk * 16 + tig * 2;
            uint32_t a0 = *(uint32_t*)&Qs[r][col];
            uint32_t a1 = *(uint32_t*)&Qs[r + 8][col];
            uint32_t a2 = *(uint32_t*)&Qs[r][col + 8];
            uint32_t a3 = *(uint32_t*)&Qs[r + 8][col + 8];
#pragma unroll
            for (int nt = 0; nt < 7; nt++) {
                uint32_t b0 = *(uint32_t*)&Ks[nt * 8 + gid][col];
                uint32_t b1 = *(uint32_t*)&Ks[nt * 8 + gid][col + 8];
                mma16816(c[nt], a0, a1, a2, a3, b0, b1);
            }
        }
#pragma unroll
        for (int nt = 0; nt < 7; nt++) {
            int cc = nt * 8 + 2 * tig;
            sc[r][cc]     = c[nt][0]; sc[r][cc+1]   = c[nt][1];
            sc[r+8][cc]   = c[nt][2]; sc[r+8][cc+1] = c[nt][3];
        }
    }
    __syncthreads();

    const float scale = 0.1767766952966369f;
    for (int idx = tid; idx < 49 * 49; idx += 128) {
        int n = idx / 49, m = idx - n * 49;
        int i1 = n / 7, j1 = n - i1 * 7;
        int i2 = m / 7, j2 = m - i2 * 7;
        float bias = rpb[((i1 - i2 + 6) * 13 + (j1 - j2 + 6)) * NHD + hh];
        float mv = (regid[n] != regid[m]) ? -100.f : 0.f;
        sc[n][m] = sc[n][m] * scale + bias + mv;
    }
    __syncthreads();

    for (int r = warp; r < 49; r += 4) {
        float v0 = sc[r][lane < 49 ? lane : 0];
        if (lane >= 49) v0 = -1e30f;
        float v1 = (lane < 17) ? sc[r][32 + lane] : -1e30f;
        float mx = fmaxf(v0, v1);
#pragma unroll
        for (int o = 16; o > 0; o >>= 1) mx = fmaxf(mx, __shfl_xor_sync(0xffffffffu, mx, o));
        float e0 = (lane < 49) ? __expf(v0 - mx) : 0.f;
        float e1 = (lane < 17) ? __expf(v1 - mx) : 0.f;
        float s = e0 + e1;
#pragma unroll
        for (int o = 16; o > 0; o >>= 1) s += __shfl_xor_sync(0xffffffffu, s, o);
        float inv = 1.f / s;
        if (lane < 49) Ps[r][lane] = __float2half(e0 * inv);
        if (lane < 17) Ps[r][32 + lane] = __float2half(e1 * inv);
    }
    __syncthreads();

    {
        float c[4][4];
#pragma unroll
        for (int nt = 0; nt < 4; nt++)
#pragma unroll
            for (int i = 0; i < 4; i++) c[nt][i] = 0.f;
        int r = warp * 16 + gid;
#pragma unroll
        for (int kk = 0; kk < 4; kk++) {
            int col = kk * 16 + tig * 2;
            uint32_t a0 = *(uint32_t*)&Ps[r][col];
            uint32_t a1 = *(uint32_t*)&Ps[r + 8][col];
            uint32_t a2 = *(uint32_t*)&Ps[r][col + 8];
            uint32_t a3 = *(uint32_t*)&Ps[r + 8][col + 8];
#pragma unroll
            for (int nt = 0; nt < 4; nt++) {
                uint32_t b0 = *(uint32_t*)&Vt[nt * 8 + gid][col];
                uint32_t b1 = *(uint32_t*)&Vt[nt * 8 + gid][col + 8];
                mma16816(c[nt], a0, a1, a2, a3, b0, b1);
            }
        }
#pragma unroll
        for (int half_ = 0; half_ < 2; half_++) {
            int n = warp * 16 + gid + half_ * 8;
            if (n < 49) {
                size_t orow = ((size_t)w * 49 + n) * CH + hh * HD;
#pragma unroll
                for (int nt = 0; nt < 4; nt++) {
                    int d = nt * 8 + 2 * tig;
                    __half2 h2 = __floats2half2_rn(c[nt][half_ * 2 + 0], c[nt][half_ * 2 + 1]);
                    *(__half2*)&g_attn[orow + d] = h2;
                }
            }
        }
    }
}

// ---------------- fp16 GEMM, ldmatrix + swizzle, BK=64 ----------------
// smem layout: per operand per stage: 128 rows x 64 halves (128B row), chunk-XOR swizzle
// EPI: 0 bias (half out), 1 bias+GELU (half out), 2 proj scatter+res (f32), 3 bias+res (f32)
#define BM 128
#define BN 128
#define BK 64
#define STG_BYTES 16384          // 128*64*2
#define SMEM_GEMM (4 * STG_BYTES)

template <int EPI>
__global__ __launch_bounds__(256, 2)
void gemm_h(const __half* __restrict__ A, const __half* __restrict__ B,
            const float* __restrict__ bias, const float* __restrict__ res,
            void* __restrict__ Cv, int M, int N, int K) {
    extern __shared__ char smem[];
    uint32_t sA0 = (uint32_t)__cvta_generic_to_shared(smem);            // A: 2 stages
    uint32_t sB0 = sA0 + 2 * STG_BYTES;                                  // B: 2 stages
    int tid = threadIdx.x;
    int lane = tid & 31, warp = tid >> 5;
    int wm = (warp >> 2) * 64, wn = (warp & 3) * 32;
    int bm = blockIdx.y * BM, bn = blockIdx.x * BN;

    float acc[4][4][4];
#pragma unroll
    for (int i = 0; i < 4; i++)
#pragma unroll
        for (int j = 0; j < 4; j++)
#pragma unroll
            for (int k = 0; k < 4; k++) acc[i][j][k] = 0.f;

    // ---- cp.async mapping: row lr (&+64), chunks lc, lc+4 ----
    int lr = tid >> 2, lc = tid & 3;
    const __half* Ab = A + (size_t)(bm + lr) * K + lc * 8;
    const __half* Bb = B + (size_t)(bn + lr) * K + lc * 8;
    uint32_t stA[4], stB[4];
    {
        int r1 = lr, r2 = lr + 64;
        stA[0] = r1 * 128 + (((lc)     ^ (r1 & 7)) << 4);
        stA[1] = r1 * 128 + (((lc + 4) ^ (r1 & 7)) << 4);
        stA[2] = r2 * 128 + (((lc)     ^ (r2 & 7)) << 4);
        stA[3] = r2 * 128 + (((lc + 4) ^ (r2 & 7)) << 4);
#pragma unroll
        for (int i = 0; i < 4; i++) stB[i] = stA[i];
    }

    // ---- ldmatrix address precompute ----
    // A: lane -> row = wm + mt*16 + (lane&7) + (lane&8); chunk = 2*kk + (lane>>4)
    uint32_t aOff[4], aXor[4];
#pragma unroll
    for (int mt = 0; mt < 4; mt++) {
        int r = wm + mt * 16 + (lane & 7) + (lane & 8);
        aOff[mt] = r * 128;
        aXor[mt] = (r & 7) << 4;
    }
    int aCs = (lane >> 4) & 1;
    // B: pair p -> row = wn + p*16 + (lane&7) + ((lane>>4)&1)*8; chunk = 2*kk + ((lane>>3)&1)
    uint32_t bOff[2], bXor[2];
#pragma unroll
    for (int p = 0; p < 2; p++) {
        int r = wn + p * 16 + (lane & 7) + ((lane >> 4) & 1) * 8;
        bOff[p] = r * 128;
        bXor[p] = (r & 7) << 4;
    }
    int bCs = (lane >> 3) & 1;

    int NIT = K / BK;
    // prologue: stage 0
    {
#pragma unroll
        for (int i = 0; i < 4; i++) {
            cp16(sA0 + stA[i], Ab + ((i >> 1) ? (size_t)64 * K : 0) + ((i & 1) ? 32 : 0));
            cp16(sB0 + stB[i], Bb + ((i >> 1) ? (size_t)64 * K : 0) + ((i & 1) ? 32 : 0));
        }
        cp_commit();
    }
    for (int it = 0; it < NIT; ++it) {
        if (it + 1 < NIT) {
            uint32_t so = ((it + 1) & 1) * STG_BYTES;
            const __half* ap = Ab + (it + 1) * BK;
            const __half* bp = Bb + (it + 1) * BK;
#pragma unroll
            for (int i = 0; i < 4; i++) {
                cp16(sA0 + so + stA[i], ap + ((i >> 1) ? (size_t)64 * K : 0) + ((i & 1) ? 32 : 0));
                cp16(sB0 + so + stB[i], bp + ((i >> 1) ? (size_t)64 * K : 0) + ((i & 1) ? 32 : 0));
            }
        }
        cp_commit();
        cp_wait1();
        __syncthreads();
        uint32_t aBase = sA0 + (it & 1) * STG_BYTES;
        uint32_t bBase = sB0 + (it & 1) * STG_BYTES;
#pragma unroll
        for (int kk = 0; kk < 4; kk++) {
            uint32_t a[4][4], b[2][4];
            uint32_t cA = ((2 * kk + aCs) << 4);
            uint32_t cB = ((2 * kk + bCs) << 4);
#pragma unroll
            for (int mt = 0; mt < 4; mt++)
                ldsm4(a[mt], aBase + aOff[mt] + (cA ^ aXor[mt]));
#pragma unroll
            for (int p = 0; p < 2; p++)
                ldsm4(b[p], bBase + bOff[p] + (cB ^ bXor[p]));
#pragma unroll
            for (int mt = 0; mt < 4; mt++)
#pragma unroll
                for (int nt = 0; nt < 4; nt++)
                    mma16816(acc[mt][nt], a[mt][0], a[mt][1], a[mt][2], a[mt][3],
                             b[nt >> 1][(nt & 1) * 2], b[nt >> 1][(nt & 1) * 2 + 1]);
        }
        __syncthreads();
    }

    // ---- epilogue ----
    int gid = lane >> 2, tig = lane & 3;
#pragma unroll
    for (int mt = 0; mt < 4; mt++) {
#pragma unroll
        for (int half_ = 0; half_ < 2; half_++) {
            int m = bm + wm + mt * 16 + gid + half_ * 8;
            size_t drow;
            if (EPI == 2) {
                int wnd = m / 49, n = m - wnd * 49;
                int bb = wnd >> 4, wl = wnd & 15;
                int wh = wl >> 2, ww = wl & 3;
                int ii = n / 7, jj = n - ii * 7;
                int h_ = wh * 7 + ii + 3; if (h_ >= 28) h_ -= 28;
                int w_ = ww * 7 + jj + 3; if (w_ >= 28) w_ -= 28;
                drow = (size_t)(bb * 784 + h_ * 28 + w_);
            } else {
                drow = (size_t)m;
            }
#pragma unroll
            for (int nt = 0; nt < 4; nt++) {
                int cc = bn + wn + nt * 8 + 2 * tig;
                float v0 = acc[mt][nt][half_ * 2 + 0] + bias[cc];
                float v1 = acc[mt][nt][half_ * 2 + 1] + bias[cc + 1];
                if (EPI == 1) { v0 = gelu_exact(v0); v1 = gelu_exact(v1); }
                if (EPI == 2 || EPI == 3) {
                    const float* rrow = res + drow * N;
                    v0 += rrow[cc]; v1 += rrow[cc + 1];
                    float2 o; o.x = v0; o.y = v1;
                    *(float2*)&((float*)Cv)[drow * N + cc] = o;
                } else {
                    __half2 h2 = __floats2half2_rn(v0, v1);
                    *(__half2*)&((__half*)Cv)[drow * N + cc] = h2;
                }
            }
        }
    }
}

// ---------------- launch ----------------
extern "C" void kernel_launch(void* const* d_in, const int* in_sizes, int n_in,
                              void* d_out, int out_size) {
    const float* x      = (const float*)d_in[0];
    const float* ln1_s  = (const float*)d_in[1];
    const float* ln1_b  = (const float*)d_in[2];
    const float* qkv_w  = (const float*)d_in[3];
    const float* qkv_b  = (const float*)d_in[4];
    const float* qkv_la = (const float*)d_in[5];
    const float* qkv_lb = (const float*)d_in[6];
    const float* rpb    = (const float*)d_in[7];
    const float* proj_w = (const float*)d_in[8];
    const float* proj_b = (const float*)d_in[9];
    const float* proj_la= (const float*)d_in[10];
    const float* proj_lb= (const float*)d_in[11];
    const float* ln2_s  = (const float*)d_in[12];
    const float* ln2_b  = (const float*)d_in[13];
    const float* fc1_w  = (const float*)d_in[14];
    const float* fc1_b  = (const float*)d_in[15];
    const float* fc1_la = (const float*)d_in[16];
    const float* fc1_lb = (const float*)d_in[17];
    const float* fc2_w  = (const float*)d_in[18];
    const float* fc2_b  = (const float*)d_in[19];
    const float* fc2_la = (const float*)d_in[20];
    const float* fc2_lb = (const float*)d_in[21];
    float* out = (float*)d_out;

    __half *wqkv, *wproj, *wfc1, *wfc2, *xw, *qkv, *attn, *xn2, *hb;
    float *x2;
    cudaGetSymbolAddress((void**)&wqkv,  g_wqkv);
    cudaGetSymbolAddress((void**)&wproj, g_wproj);
    cudaGetSymbolAddress((void**)&wfc1,  g_wfc1);
    cudaGetSymbolAddress((void**)&wfc2,  g_wfc2);
    cudaGetSymbolAddress((void**)&xw,    g_xw);
    cudaGetSymbolAddress((void**)&qkv,   g_qkv);
    cudaGetSymbolAddress((void**)&attn,  g_attn);
    cudaGetSymbolAddress((void**)&x2,    g_x2);
    cudaGetSymbolAddress((void**)&xn2,   g_xn2);
    cudaGetSymbolAddress((void**)&hb,    g_hbuf);

    static bool attr_done = false;
    if (!attr_done) {
        cudaFuncSetAttribute(gemm_h<0>, cudaFuncAttributeMaxDynamicSharedMemorySize, SMEM_GEMM);
        cudaFuncSetAttribute(gemm_h<1>, cudaFuncAttributeMaxDynamicSharedMemorySize, SMEM_GEMM);
        cudaFuncSetAttribute(gemm_h<2>, cudaFuncAttributeMaxDynamicSharedMemorySize, SMEM_GEMM);
        cudaFuncSetAttribute(gemm_h<3>, cudaFuncAttributeMaxDynamicSharedMemorySize, SMEM_GEMM);
        attr_done = true;
    }

    // 1) fold LoRA into weights ([N][K], half)
    fuse_w_kernel<<<(C3 * CH + 255) / 256, 256>>>(qkv_w,  qkv_la,  qkv_lb,  wqkv,  C3, CH);
    fuse_w_kernel<<<(CH * CH + 255) / 256, 256>>>(proj_w, proj_la, proj_lb, wproj, CH, CH);
    fuse_w_kernel<<<(FF * CH + 255) / 256, 256>>>(fc1_w,  fc1_la,  fc1_lb,  wfc1,  FF, CH);
    fuse_w_kernel<<<(CH * FF + 255) / 256, 256>>>(fc2_w,  fc2_la,  fc2_lb,  wfc2,  CH, FF);

    // 2) LN1 + shift + window partition
    ln_kernel<true><<<TOK, 256>>>(x, ln1_s, ln1_b, xw);

    // 3) QKV GEMM
    gemm_h<0><<<dim3(C3 / BN, TOK / BM), 256, SMEM_GEMM>>>(xw, wqkv, qkv_b, nullptr, qkv, TOK, C3, CH);

    // 4) windowed attention
    attn_kernel<<<dim3(NWIN, NHD), 128>>>(rpb);

    // 5) proj GEMM + window reverse + reverse shift + residual
    gemm_h<2><<<dim3(CH / BN, TOK / BM), 256, SMEM_GEMM>>>(attn, wproj, proj_b, x, x2, TOK, CH, CH);

    // 6) LN2
    ln_kernel<false><<<TOK, 256>>>(x2, ln2_s, ln2_b, xn2);

    // 7) fc1 + GELU
    gemm_h<1><<<dim3(FF / BN, TOK / BM), 256, SMEM_GEMM>>>(xn2, wfc1, fc1_b, nullptr, hb, TOK, FF, CH);

    // 8) fc2 + residual -> out
    gemm_h<3><<<dim3(CH / BN, TOK / BM), 256, SMEM_GEMM>>>(hb, wfc2, fc2_b, x2, out, TOK, CH, FF);
}